// round 1
// baseline (speedup 1.0000x reference)
#include <cuda_runtime.h>

#define N_NODES 100000
#define N_EDGES 1250000
#define DIN 128
#define HID 64
#define DOUT 40

// ---- scratch (static device arrays; no allocation allowed) ----
__device__ float g_h1[(size_t)N_NODES * HID];    // X @ W1
__device__ float g_a1[(size_t)N_NODES * HID];    // relu(aggregate(h1)+b1)
__device__ float g_h2[(size_t)N_NODES * DOUT];   // a1 @ W2
__device__ float g_dinv[N_NODES];
__device__ int   g_cnt[N_NODES];
__device__ int   g_rowptr[N_NODES + 1];
__device__ int   g_cursor[N_NODES];
__device__ int   g_col[N_EDGES];

// ---------------------------------------------------------------
__global__ void k_zero_cnt() {
    int i = blockIdx.x * blockDim.x + threadIdx.x;
    if (i < N_NODES) g_cnt[i] = 0;
}

__global__ void k_count(const int* __restrict__ ei) {
    int e = blockIdx.x * blockDim.x + threadIdx.x;
    if (e < N_EDGES) atomicAdd(&g_cnt[ei[N_EDGES + e]], 1);
}

// single-block hierarchical scan: g_rowptr = exclusive scan of g_cnt
__global__ __launch_bounds__(1024) void k_scan() {
    __shared__ int wsum[32];
    __shared__ int s_carry;
    int tid = threadIdx.x, lane = tid & 31, wid = tid >> 5;
    if (tid == 0) { s_carry = 0; g_rowptr[0] = 0; }
    __syncthreads();
    for (int base = 0; base < N_NODES; base += 4096) {
        int idx = base + tid * 4;
        int v0 = 0, v1 = 0, v2 = 0, v3 = 0;
        if (idx + 3 < N_NODES) {
            int4 t = *(const int4*)(g_cnt + idx);
            v0 = t.x; v1 = t.y; v2 = t.z; v3 = t.w;
        } else {
            if (idx     < N_NODES) v0 = g_cnt[idx];
            if (idx + 1 < N_NODES) v1 = g_cnt[idx + 1];
            if (idx + 2 < N_NODES) v2 = g_cnt[idx + 2];
            if (idx + 3 < N_NODES) v3 = g_cnt[idx + 3];
        }
        int s1 = v0 + v1, s2 = s1 + v2, s3 = s2 + v3;
        int xi = s3;
        #pragma unroll
        for (int o = 1; o < 32; o <<= 1) {
            int y = __shfl_up_sync(0xffffffffu, xi, o);
            if (lane >= o) xi += y;
        }
        if (lane == 31) wsum[wid] = xi;
        __syncthreads();
        if (wid == 0) {
            int wv = wsum[lane];
            #pragma unroll
            for (int o = 1; o < 32; o <<= 1) {
                int y = __shfl_up_sync(0xffffffffu, wv, o);
                if (lane >= o) wv += y;
            }
            wsum[lane] = wv;
        }
        __syncthreads();
        int excl = s_carry + (wid ? wsum[wid - 1] : 0) + (xi - s3);
        if (idx     < N_NODES) g_rowptr[idx + 1] = excl + v0;
        if (idx + 1 < N_NODES) g_rowptr[idx + 2] = excl + s1;
        if (idx + 2 < N_NODES) g_rowptr[idx + 3] = excl + s2;
        if (idx + 3 < N_NODES) g_rowptr[idx + 4] = excl + s3;
        __syncthreads();
        if (tid == 0) s_carry += wsum[31];
        __syncthreads();
    }
}

__global__ void k_dinv_cursor() {
    int i = blockIdx.x * blockDim.x + threadIdx.x;
    if (i < N_NODES) {
        g_dinv[i] = rsqrtf((float)(g_cnt[i] + 1));   // +1 self-loop
        g_cursor[i] = g_rowptr[i];
    }
}

__global__ void k_fill(const int* __restrict__ ei) {
    int e = blockIdx.x * blockDim.x + threadIdx.x;
    if (e < N_EDGES) {
        int dst = ei[N_EDGES + e];
        int pos = atomicAdd(&g_cursor[dst], 1);
        g_col[pos] = ei[e];   // src
    }
}

// ---------------------------------------------------------------
// GEMM1: g_h1[N,64] = x[N,128] @ W1[128,64]
// 64 rows/block, 256 threads, K chunked into 2x64 (fits 48KB static smem)
__global__ __launch_bounds__(256) void k_gemm1(const float* __restrict__ x,
                                               const float* __restrict__ W1) {
    __shared__ float Ws[64 * 64];    // [kk][c]
    __shared__ float Xs[64 * 68];    // [r][kk], padded stride
    int tid = threadIdx.x;
    int row0 = blockIdx.x * 64;
    int tx = tid & 15, ty = tid >> 4;

    float acc[4][4];
    #pragma unroll
    for (int i = 0; i < 4; i++)
        #pragma unroll
        for (int j = 0; j < 4; j++) acc[i][j] = 0.f;

    for (int kc = 0; kc < 2; kc++) {
        // W chunk: rows kc*64..kc*64+63, contiguous 4096 floats
        const float4* wg = (const float4*)(W1 + (size_t)kc * 64 * HID);
        #pragma unroll
        for (int i = tid; i < 64 * 16; i += 256) ((float4*)Ws)[i] = wg[i];
        // X chunk
        for (int i = tid; i < 64 * 16; i += 256) {
            int r = i >> 4, kv = i & 15;
            int row = row0 + r;
            float4 v = make_float4(0.f, 0.f, 0.f, 0.f);
            if (row < N_NODES)
                v = *(const float4*)(x + (size_t)row * DIN + kc * 64 + kv * 4);
            *(float4*)(Xs + r * 68 + kv * 4) = v;
        }
        __syncthreads();
        const float* xb = Xs + (ty * 4) * 68;
        #pragma unroll 4
        for (int k = 0; k < 64; k++) {
            float4 wv = *(const float4*)(Ws + k * 64 + tx * 4);
            float x0 = xb[k], x1 = xb[68 + k], x2 = xb[136 + k], x3 = xb[204 + k];
            acc[0][0] = fmaf(x0, wv.x, acc[0][0]);
            acc[0][1] = fmaf(x0, wv.y, acc[0][1]);
            acc[0][2] = fmaf(x0, wv.z, acc[0][2]);
            acc[0][3] = fmaf(x0, wv.w, acc[0][3]);
            acc[1][0] = fmaf(x1, wv.x, acc[1][0]);
            acc[1][1] = fmaf(x1, wv.y, acc[1][1]);
            acc[1][2] = fmaf(x1, wv.z, acc[1][2]);
            acc[1][3] = fmaf(x1, wv.w, acc[1][3]);
            acc[2][0] = fmaf(x2, wv.x, acc[2][0]);
            acc[2][1] = fmaf(x2, wv.y, acc[2][1]);
            acc[2][2] = fmaf(x2, wv.z, acc[2][2]);
            acc[2][3] = fmaf(x2, wv.w, acc[2][3]);
            acc[3][0] = fmaf(x3, wv.x, acc[3][0]);
            acc[3][1] = fmaf(x3, wv.y, acc[3][1]);
            acc[3][2] = fmaf(x3, wv.z, acc[3][2]);
            acc[3][3] = fmaf(x3, wv.w, acc[3][3]);
        }
        __syncthreads();
    }
    #pragma unroll
    for (int i = 0; i < 4; i++) {
        int row = row0 + ty * 4 + i;
        if (row < N_NODES)
            *(float4*)(g_h1 + (size_t)row * HID + tx * 4) =
                make_float4(acc[i][0], acc[i][1], acc[i][2], acc[i][3]);
    }
}

// GEMM2: g_h2[N,40] = g_a1[N,64] @ W2[64,40]; 128 rows/block, 1 row/thread
__global__ __launch_bounds__(128) void k_gemm2(const float* __restrict__ W2) {
    __shared__ float Ws[HID * DOUT];   // 10KB, [k][j]
    __shared__ float Xs[128 * 65];     // 33.3KB, padded
    int tid = threadIdx.x;
    int row0 = blockIdx.x * 128;

    #pragma unroll
    for (int i = tid; i < HID * DOUT / 4; i += 128)
        ((float4*)Ws)[i] = ((const float4*)W2)[i];
    for (int i = tid; i < 128 * 16; i += 128) {
        int r = i >> 4, kv = i & 15;
        int row = row0 + r;
        float4 v = make_float4(0.f, 0.f, 0.f, 0.f);
        if (row < N_NODES)
            v = *(const float4*)(g_a1 + (size_t)row * HID + kv * 4);
        float* p = Xs + r * 65 + kv * 4;
        p[0] = v.x; p[1] = v.y; p[2] = v.z; p[3] = v.w;
    }
    __syncthreads();

    float acc[DOUT];
    #pragma unroll
    for (int j = 0; j < DOUT; j++) acc[j] = 0.f;
    const float* xr = Xs + tid * 65;
    #pragma unroll 4
    for (int k = 0; k < HID; k++) {
        float xv = xr[k];
        const float4* wr = (const float4*)(Ws + k * DOUT);
        #pragma unroll
        for (int j = 0; j < 10; j++) {
            float4 wv = wr[j];
            acc[4 * j + 0] = fmaf(xv, wv.x, acc[4 * j + 0]);
            acc[4 * j + 1] = fmaf(xv, wv.y, acc[4 * j + 1]);
            acc[4 * j + 2] = fmaf(xv, wv.z, acc[4 * j + 2]);
            acc[4 * j + 3] = fmaf(xv, wv.w, acc[4 * j + 3]);
        }
    }
    int row = row0 + tid;
    if (row < N_NODES) {
        float4* o = (float4*)(g_h2 + (size_t)row * DOUT);
        #pragma unroll
        for (int j = 0; j < 10; j++)
            o[j] = make_float4(acc[4 * j], acc[4 * j + 1], acc[4 * j + 2], acc[4 * j + 3]);
    }
}

// ---------------------------------------------------------------
// agg1: warp per node, 64 dims (2 floats/lane); out = relu(sum + b1)
__global__ __launch_bounds__(256) void k_agg1(const float* __restrict__ b1) {
    int v = (blockIdx.x * blockDim.x + threadIdx.x) >> 5;
    int lane = threadIdx.x & 31;
    if (v >= N_NODES) return;
    float dv = g_dinv[v];
    float2 acc = ((const float2*)(g_h1 + (size_t)v * HID))[lane];
    float sw = dv * dv;
    acc.x *= sw; acc.y *= sw;
    int start = g_rowptr[v], end = g_rowptr[v + 1];
    for (int base = start; base < end; base += 32) {
        int e = base + lane;
        int s = 0; float w = 0.f;
        if (e < end) { s = g_col[e]; w = g_dinv[s] * dv; }
        int cnt = min(32, end - base);
        for (int j = 0; j < cnt; j++) {
            int   ss = __shfl_sync(0xffffffffu, s, j);
            float ww = __shfl_sync(0xffffffffu, w, j);
            float2 hh = ((const float2*)(g_h1 + (size_t)ss * HID))[lane];
            acc.x = fmaf(ww, hh.x, acc.x);
            acc.y = fmaf(ww, hh.y, acc.y);
        }
    }
    float2 bb = ((const float2*)b1)[lane];
    acc.x = fmaxf(acc.x + bb.x, 0.f);
    acc.y = fmaxf(acc.y + bb.y, 0.f);
    ((float2*)(g_a1 + (size_t)v * HID))[lane] = acc;
}

// agg2: warp per node, 40 dims (lane + optional lane+32); out = sum + b2
__global__ __launch_bounds__(256) void k_agg2(const float* __restrict__ b2,
                                              float* __restrict__ out) {
    int v = (blockIdx.x * blockDim.x + threadIdx.x) >> 5;
    int lane = threadIdx.x & 31;
    if (v >= N_NODES) return;
    float dv = g_dinv[v];
    bool p2 = lane < (DOUT - 32);
    const float* hv = g_h2 + (size_t)v * DOUT;
    float sw = dv * dv;
    float a0 = hv[lane] * sw;
    float a1 = p2 ? hv[32 + lane] * sw : 0.f;
    int start = g_rowptr[v], end = g_rowptr[v + 1];
    for (int base = start; base < end; base += 32) {
        int e = base + lane;
        int s = 0; float w = 0.f;
        if (e < end) { s = g_col[e]; w = g_dinv[s] * dv; }
        int cnt = min(32, end - base);
        for (int j = 0; j < cnt; j++) {
            int   ss = __shfl_sync(0xffffffffu, s, j);
            float ww = __shfl_sync(0xffffffffu, w, j);
            const float* hs = g_h2 + (size_t)ss * DOUT;
            a0 = fmaf(ww, hs[lane], a0);
            if (p2) a1 = fmaf(ww, hs[32 + lane], a1);
        }
    }
    float* ov = out + (size_t)v * DOUT;
    ov[lane] = a0 + b2[lane];
    if (p2) ov[32 + lane] = a1 + b2[32 + lane];
}

// ---------------------------------------------------------------
extern "C" void kernel_launch(void* const* d_in, const int* in_sizes, int n_in,
                              void* d_out, int out_size) {
    const float* x  = (const float*)d_in[0];
    const float* W1 = (const float*)d_in[1];
    const float* b1 = (const float*)d_in[2];
    const float* W2 = (const float*)d_in[3];
    const float* b2 = (const float*)d_in[4];
    const int*   ei = (const int*)d_in[5];
    float* out = (float*)d_out;

    k_zero_cnt<<<(N_NODES + 255) / 256, 256>>>();
    k_count<<<(N_EDGES + 255) / 256, 256>>>(ei);
    k_scan<<<1, 1024>>>();
    k_dinv_cursor<<<(N_NODES + 255) / 256, 256>>>();
    k_fill<<<(N_EDGES + 255) / 256, 256>>>(ei);

    k_gemm1<<<(N_NODES + 63) / 64, 256>>>(x, W1);
    k_agg1<<<(N_NODES * 32 + 255) / 256, 256>>>(b1);
    k_gemm2<<<(N_NODES + 127) / 128, 128>>>(W2);
    k_agg2<<<(N_NODES * 32 + 255) / 256, 256>>>(b2, out);
}

// round 2
// speedup vs baseline: 1.0064x; 1.0064x over previous
#include <cuda_runtime.h>

#define N_NODES 100000
#define N_EDGES 1250000
#define DIN 128
#define HID 64
#define DOUT 40

// ---- scratch (static device arrays; no allocation allowed) ----
__device__ float g_h1[(size_t)N_NODES * HID];    // X @ W1
__device__ float g_a1[(size_t)N_NODES * HID];    // relu(aggregate(h1)+b1)
__device__ float g_h2[(size_t)N_NODES * DOUT];   // a1 @ W2
__device__ float g_dinv[N_NODES];
__device__ int   g_cnt[N_NODES];
__device__ int   g_rowptr[N_NODES + 1];
__device__ int   g_cursor[N_NODES];
__device__ int   g_col[N_EDGES];

// ---------------------------------------------------------------
__global__ void k_zero_cnt() {
    int i = blockIdx.x * blockDim.x + threadIdx.x;
    if (i < N_NODES) g_cnt[i] = 0;
}

__global__ void k_count(const int* __restrict__ ei) {
    int e = blockIdx.x * blockDim.x + threadIdx.x;
    if (e < N_EDGES) atomicAdd(&g_cnt[ei[N_EDGES + e]], 1);
}

// single-block hierarchical scan: g_rowptr = exclusive scan of g_cnt
__global__ __launch_bounds__(1024) void k_scan() {
    __shared__ int wsum[32];
    __shared__ int s_carry;
    int tid = threadIdx.x, lane = tid & 31, wid = tid >> 5;
    if (tid == 0) { s_carry = 0; g_rowptr[0] = 0; }
    __syncthreads();
    for (int base = 0; base < N_NODES; base += 4096) {
        int idx = base + tid * 4;
        int v0 = 0, v1 = 0, v2 = 0, v3 = 0;
        if (idx + 3 < N_NODES) {
            int4 t = *(const int4*)(g_cnt + idx);
            v0 = t.x; v1 = t.y; v2 = t.z; v3 = t.w;
        } else {
            if (idx     < N_NODES) v0 = g_cnt[idx];
            if (idx + 1 < N_NODES) v1 = g_cnt[idx + 1];
            if (idx + 2 < N_NODES) v2 = g_cnt[idx + 2];
            if (idx + 3 < N_NODES) v3 = g_cnt[idx + 3];
        }
        int s1 = v0 + v1, s2 = s1 + v2, s3 = s2 + v3;
        int xi = s3;
        #pragma unroll
        for (int o = 1; o < 32; o <<= 1) {
            int y = __shfl_up_sync(0xffffffffu, xi, o);
            if (lane >= o) xi += y;
        }
        if (lane == 31) wsum[wid] = xi;
        __syncthreads();
        if (wid == 0) {
            int wv = wsum[lane];
            #pragma unroll
            for (int o = 1; o < 32; o <<= 1) {
                int y = __shfl_up_sync(0xffffffffu, wv, o);
                if (lane >= o) wv += y;
            }
            wsum[lane] = wv;
        }
        __syncthreads();
        int excl = s_carry + (wid ? wsum[wid - 1] : 0) + (xi - s3);
        if (idx     < N_NODES) g_rowptr[idx + 1] = excl + v0;
        if (idx + 1 < N_NODES) g_rowptr[idx + 2] = excl + s1;
        if (idx + 2 < N_NODES) g_rowptr[idx + 3] = excl + s2;
        if (idx + 3 < N_NODES) g_rowptr[idx + 4] = excl + s3;
        __syncthreads();
        if (tid == 0) s_carry += wsum[31];
        __syncthreads();
    }
}

__global__ void k_dinv_cursor() {
    int i = blockIdx.x * blockDim.x + threadIdx.x;
    if (i < N_NODES) {
        g_dinv[i] = rsqrtf((float)(g_cnt[i] + 1));   // +1 self-loop
        g_cursor[i] = g_rowptr[i];
    }
}

__global__ void k_fill(const int* __restrict__ ei) {
    int e = blockIdx.x * blockDim.x + threadIdx.x;
    if (e < N_EDGES) {
        int dst = ei[N_EDGES + e];
        int pos = atomicAdd(&g_cursor[dst], 1);
        g_col[pos] = ei[e];   // src
    }
}

// ---------------------------------------------------------------
// GEMM1: g_h1[N,64] = x[N,128] @ W1[128,64]
// 64 rows/block, 256 threads, K chunked into 2x64 (fits 48KB static smem)
__global__ __launch_bounds__(256) void k_gemm1(const float* __restrict__ x,
                                               const float* __restrict__ W1) {
    __shared__ float Ws[64 * 64];    // [kk][c]
    __shared__ float Xs[64 * 68];    // [r][kk], padded stride
    int tid = threadIdx.x;
    int row0 = blockIdx.x * 64;
    int tx = tid & 15, ty = tid >> 4;

    float acc[4][4];
    #pragma unroll
    for (int i = 0; i < 4; i++)
        #pragma unroll
        for (int j = 0; j < 4; j++) acc[i][j] = 0.f;

    for (int kc = 0; kc < 2; kc++) {
        // W chunk: rows kc*64..kc*64+63, contiguous 4096 floats
        const float4* wg = (const float4*)(W1 + (size_t)kc * 64 * HID);
        #pragma unroll
        for (int i = tid; i < 64 * 16; i += 256) ((float4*)Ws)[i] = wg[i];
        // X chunk
        for (int i = tid; i < 64 * 16; i += 256) {
            int r = i >> 4, kv = i & 15;
            int row = row0 + r;
            float4 v = make_float4(0.f, 0.f, 0.f, 0.f);
            if (row < N_NODES)
                v = *(const float4*)(x + (size_t)row * DIN + kc * 64 + kv * 4);
            *(float4*)(Xs + r * 68 + kv * 4) = v;
        }
        __syncthreads();
        const float* xb = Xs + (ty * 4) * 68;
        #pragma unroll 4
        for (int k = 0; k < 64; k++) {
            float4 wv = *(const float4*)(Ws + k * 64 + tx * 4);
            float x0 = xb[k], x1 = xb[68 + k], x2 = xb[136 + k], x3 = xb[204 + k];
            acc[0][0] = fmaf(x0, wv.x, acc[0][0]);
            acc[0][1] = fmaf(x0, wv.y, acc[0][1]);
            acc[0][2] = fmaf(x0, wv.z, acc[0][2]);
            acc[0][3] = fmaf(x0, wv.w, acc[0][3]);
            acc[1][0] = fmaf(x1, wv.x, acc[1][0]);
            acc[1][1] = fmaf(x1, wv.y, acc[1][1]);
            acc[1][2] = fmaf(x1, wv.z, acc[1][2]);
            acc[1][3] = fmaf(x1, wv.w, acc[1][3]);
            acc[2][0] = fmaf(x2, wv.x, acc[2][0]);
            acc[2][1] = fmaf(x2, wv.y, acc[2][1]);
            acc[2][2] = fmaf(x2, wv.z, acc[2][2]);
            acc[2][3] = fmaf(x2, wv.w, acc[2][3]);
            acc[3][0] = fmaf(x3, wv.x, acc[3][0]);
            acc[3][1] = fmaf(x3, wv.y, acc[3][1]);
            acc[3][2] = fmaf(x3, wv.z, acc[3][2]);
            acc[3][3] = fmaf(x3, wv.w, acc[3][3]);
        }
        __syncthreads();
    }
    #pragma unroll
    for (int i = 0; i < 4; i++) {
        int row = row0 + ty * 4 + i;
        if (row < N_NODES)
            *(float4*)(g_h1 + (size_t)row * HID + tx * 4) =
                make_float4(acc[i][0], acc[i][1], acc[i][2], acc[i][3]);
    }
}

// GEMM2: g_h2[N,40] = g_a1[N,64] @ W2[64,40]; 128 rows/block, 1 row/thread
__global__ __launch_bounds__(128) void k_gemm2(const float* __restrict__ W2) {
    __shared__ float Ws[HID * DOUT];   // 10KB, [k][j]
    __shared__ float Xs[128 * 65];     // 33.3KB, padded
    int tid = threadIdx.x;
    int row0 = blockIdx.x * 128;

    #pragma unroll
    for (int i = tid; i < HID * DOUT / 4; i += 128)
        ((float4*)Ws)[i] = ((const float4*)W2)[i];
    for (int i = tid; i < 128 * 16; i += 128) {
        int r = i >> 4, kv = i & 15;
        int row = row0 + r;
        float4 v = make_float4(0.f, 0.f, 0.f, 0.f);
        if (row < N_NODES)
            v = *(const float4*)(g_a1 + (size_t)row * HID + kv * 4);
        float* p = Xs + r * 65 + kv * 4;
        p[0] = v.x; p[1] = v.y; p[2] = v.z; p[3] = v.w;
    }
    __syncthreads();

    float acc[DOUT];
    #pragma unroll
    for (int j = 0; j < DOUT; j++) acc[j] = 0.f;
    const float* xr = Xs + tid * 65;
    #pragma unroll 4
    for (int k = 0; k < HID; k++) {
        float xv = xr[k];
        const float4* wr = (const float4*)(Ws + k * DOUT);
        #pragma unroll
        for (int j = 0; j < 10; j++) {
            float4 wv = wr[j];
            acc[4 * j + 0] = fmaf(xv, wv.x, acc[4 * j + 0]);
            acc[4 * j + 1] = fmaf(xv, wv.y, acc[4 * j + 1]);
            acc[4 * j + 2] = fmaf(xv, wv.z, acc[4 * j + 2]);
            acc[4 * j + 3] = fmaf(xv, wv.w, acc[4 * j + 3]);
        }
    }
    int row = row0 + tid;
    if (row < N_NODES) {
        float4* o = (float4*)(g_h2 + (size_t)row * DOUT);
        #pragma unroll
        for (int j = 0; j < 10; j++)
            o[j] = make_float4(acc[4 * j], acc[4 * j + 1], acc[4 * j + 2], acc[4 * j + 3]);
    }
}

// ---------------------------------------------------------------
// agg1: warp per node, 64 dims (2 floats/lane); out = relu(sum + b1)
__global__ __launch_bounds__(256) void k_agg1(const float* __restrict__ b1) {
    int v = (blockIdx.x * blockDim.x + threadIdx.x) >> 5;
    int lane = threadIdx.x & 31;
    if (v >= N_NODES) return;
    float dv = g_dinv[v];
    float2 acc = ((const float2*)(g_h1 + (size_t)v * HID))[lane];
    float sw = dv * dv;
    acc.x *= sw; acc.y *= sw;
    int start = g_rowptr[v], end = g_rowptr[v + 1];
    for (int base = start; base < end; base += 32) {
        int e = base + lane;
        int s = 0; float w = 0.f;
        if (e < end) { s = g_col[e]; w = g_dinv[s] * dv; }
        int cnt = min(32, end - base);
        for (int j = 0; j < cnt; j++) {
            int   ss = __shfl_sync(0xffffffffu, s, j);
            float ww = __shfl_sync(0xffffffffu, w, j);
            float2 hh = ((const float2*)(g_h1 + (size_t)ss * HID))[lane];
            acc.x = fmaf(ww, hh.x, acc.x);
            acc.y = fmaf(ww, hh.y, acc.y);
        }
    }
    float2 bb = ((const float2*)b1)[lane];
    acc.x = fmaxf(acc.x + bb.x, 0.f);
    acc.y = fmaxf(acc.y + bb.y, 0.f);
    ((float2*)(g_a1 + (size_t)v * HID))[lane] = acc;
}

// agg2: warp per node, 40 dims (lane + optional lane+32); out = sum + b2
__global__ __launch_bounds__(256) void k_agg2(const float* __restrict__ b2,
                                              float* __restrict__ out) {
    int v = (blockIdx.x * blockDim.x + threadIdx.x) >> 5;
    int lane = threadIdx.x & 31;
    if (v >= N_NODES) return;
    float dv = g_dinv[v];
    bool p2 = lane < (DOUT - 32);
    const float* hv = g_h2 + (size_t)v * DOUT;
    float sw = dv * dv;
    float a0 = hv[lane] * sw;
    float a1 = p2 ? hv[32 + lane] * sw : 0.f;
    int start = g_rowptr[v], end = g_rowptr[v + 1];
    for (int base = start; base < end; base += 32) {
        int e = base + lane;
        int s = 0; float w = 0.f;
        if (e < end) { s = g_col[e]; w = g_dinv[s] * dv; }
        int cnt = min(32, end - base);
        for (int j = 0; j < cnt; j++) {
            int   ss = __shfl_sync(0xffffffffu, s, j);
            float ww = __shfl_sync(0xffffffffu, w, j);
            const float* hs = g_h2 + (size_t)ss * DOUT;
            a0 = fmaf(ww, hs[lane], a0);
            if (p2) a1 = fmaf(ww, hs[32 + lane], a1);
        }
    }
    float* ov = out + (size_t)v * DOUT;
    ov[lane] = a0 + b2[lane];
    if (p2) ov[32 + lane] = a1 + b2[32 + lane];
}

// ---------------------------------------------------------------
extern "C" void kernel_launch(void* const* d_in, const int* in_sizes, int n_in,
                              void* d_out, int out_size) {
    const float* x  = (const float*)d_in[0];
    const float* W1 = (const float*)d_in[1];
    const float* b1 = (const float*)d_in[2];
    const float* W2 = (const float*)d_in[3];
    const float* b2 = (const float*)d_in[4];
    const int*   ei = (const int*)d_in[5];
    float* out = (float*)d_out;

    k_zero_cnt<<<(N_NODES + 255) / 256, 256>>>();
    k_count<<<(N_EDGES + 255) / 256, 256>>>(ei);
    k_scan<<<1, 1024>>>();
    k_dinv_cursor<<<(N_NODES + 255) / 256, 256>>>();
    k_fill<<<(N_EDGES + 255) / 256, 256>>>(ei);

    k_gemm1<<<(N_NODES + 63) / 64, 256>>>(x, W1);
    k_agg1<<<(N_NODES * 32 + 255) / 256, 256>>>(b1);
    k_gemm2<<<(N_NODES + 127) / 128, 128>>>(W2);
    k_agg2<<<(N_NODES * 32 + 255) / 256, 256>>>(b2, out);
}

// round 3
// speedup vs baseline: 1.1290x; 1.1218x over previous
#include <cuda_runtime.h>

#define N_NODES 100000
#define N_EDGES 1250000
#define DIN 128
#define HID 64
#define DOUT 40

#define BM 128
#define BK 32
#define GEMM1_BLOCKS ((N_NODES + BM - 1) / BM)   // 782
#define FILL_BLOCKS  ((N_EDGES + 255) / 256)     // 4883
#define SCAN_BLOCKS  ((N_NODES + 1023) / 1024)   // 98

typedef unsigned long long ull;

// ---- scratch ----
__device__ float g_h1[(size_t)N_NODES * HID];
__device__ float g_a1[(size_t)N_NODES * HID];
__device__ float g_h2[(size_t)N_NODES * DOUT];
__device__ float g_dinv[N_NODES];
__device__ int   g_cnt[N_NODES];
__device__ int   g_rowptr[N_NODES + 1];
__device__ int   g_cursor[N_NODES];
__device__ int   g_col[N_EDGES];
__device__ int   g_bsum[128];
__device__ int   g_boff[128];

// ---- packed fp32x2 helpers (Blackwell FFMA2) ----
__device__ __forceinline__ void ffma2(ull& d, ull a, ull b) {
    asm("fma.rn.f32x2 %0, %1, %2, %0;" : "+l"(d) : "l"(a), "l"(b));
}
__device__ __forceinline__ ull fpack(float v) {
    ull r; asm("mov.b64 %0, {%1, %1};" : "=l"(r) : "f"(v)); return r;
}
__device__ __forceinline__ float2 u2f2(ull u) {
    float2 f; asm("mov.b64 {%0, %1}, %2;" : "=f"(f.x), "=f"(f.y) : "l"(u)); return f;
}

// ---------------------------------------------------------------
__global__ void k_zero_cnt() {
    int i = blockIdx.x * blockDim.x + threadIdx.x;
    if (i < N_NODES) g_cnt[i] = 0;
}

__global__ void k_count(const int* __restrict__ ei) {
    int e = blockIdx.x * blockDim.x + threadIdx.x;
    if (e < N_EDGES) atomicAdd(&g_cnt[ei[N_EDGES + e]], 1);
}

// per-block exclusive scan of g_cnt into g_rowptr (local), block totals to g_bsum;
// also computes dinv
__global__ __launch_bounds__(1024) void k_scanA() {
    __shared__ int wsum[32];
    int t = threadIdx.x, lane = t & 31, wid = t >> 5;
    int i = blockIdx.x * 1024 + t;
    int v = (i < N_NODES) ? g_cnt[i] : 0;
    if (i < N_NODES) g_dinv[i] = rsqrtf((float)(v + 1));
    int xi = v;
    #pragma unroll
    for (int o = 1; o < 32; o <<= 1) {
        int y = __shfl_up_sync(0xffffffffu, xi, o);
        if (lane >= o) xi += y;
    }
    if (lane == 31) wsum[wid] = xi;
    __syncthreads();
    if (wid == 0) {
        int wv = wsum[lane];
        #pragma unroll
        for (int o = 1; o < 32; o <<= 1) {
            int y = __shfl_up_sync(0xffffffffu, wv, o);
            if (lane >= o) wv += y;
        }
        wsum[lane] = wv;
    }
    __syncthreads();
    int excl = (wid ? wsum[wid - 1] : 0) + (xi - v);
    if (i < N_NODES) g_rowptr[i] = excl;
    if (t == 0) g_bsum[blockIdx.x] = wsum[31];
}

// 1-warp scan of SCAN_BLOCKS block totals
__global__ void k_scanB() {
    int lane = threadIdx.x;
    int carry = 0;
    for (int base = 0; base < SCAN_BLOCKS; base += 32) {
        int idx = base + lane;
        int v = (idx < SCAN_BLOCKS) ? g_bsum[idx] : 0;
        int xi = v;
        #pragma unroll
        for (int o = 1; o < 32; o <<= 1) {
            int y = __shfl_up_sync(0xffffffffu, xi, o);
            if (lane >= o) xi += y;
        }
        if (idx < SCAN_BLOCKS) g_boff[idx] = carry + xi - v;
        carry += __shfl_sync(0xffffffffu, xi, 31);
    }
}

// add block offsets; init cursor; finalize rowptr[N]
__global__ void k_scanC() {
    int i = blockIdx.x * blockDim.x + threadIdx.x;
    if (i < N_NODES) {
        int r = g_rowptr[i] + g_boff[i >> 10];
        g_rowptr[i] = r;
        g_cursor[i] = r;
    }
    if (i == 0) g_rowptr[N_NODES] = N_EDGES;
}

// ---------------------------------------------------------------
// Fused: blocks [0, GEMM1_BLOCKS) compute g_h1 = x @ W1 (f32x2 path);
//        blocks [GEMM1_BLOCKS, ...) do CSR fill (independent work).
__global__ __launch_bounds__(256) void k_fill_gemm1(const int* __restrict__ ei,
                                                    const float* __restrict__ x,
                                                    const float* __restrict__ W1) {
    __shared__ __align__(16) float Ws[BK * 64];   // 8 KB, [k][c]
    __shared__ float2 Xs2[BM * 33];               // 33 KB, duplicated pairs, padded stride
    int tid = threadIdx.x;

    if (blockIdx.x >= GEMM1_BLOCKS) {
        int e = (blockIdx.x - GEMM1_BLOCKS) * 256 + tid;
        if (e < N_EDGES) {
            int dst = ei[N_EDGES + e];
            int pos = atomicAdd(&g_cursor[dst], 1);
            g_col[pos] = ei[e];
        }
        return;
    }

    int tx = tid & 7, ty = tid >> 3;          // 8 col-groups x 32 row-groups
    int row0 = blockIdx.x * BM;

    ull acc[4][4];
    #pragma unroll
    for (int i = 0; i < 4; i++)
        #pragma unroll
        for (int j = 0; j < 4; j++) acc[i][j] = 0ull;

    for (int kc = 0; kc < DIN / BK; kc++) {
        // W chunk: 32x64 floats, contiguous
        const float4* wg = (const float4*)(W1 + (size_t)kc * BK * 64);
        ((float4*)Ws)[tid]       = wg[tid];
        ((float4*)Ws)[tid + 256] = wg[tid + 256];
        // X chunk: 128 rows x 32 k, stored as duplicated {v,v} pairs
        #pragma unroll
        for (int p = 0; p < 4; p++) {
            int f = tid + p * 256;             // 0..1023
            int r = f >> 3, kq = f & 7;
            int row = row0 + r;
            float4 v = make_float4(0.f, 0.f, 0.f, 0.f);
            if (row < N_NODES)
                v = *(const float4*)(x + (size_t)row * DIN + kc * BK + kq * 4);
            float2* d = Xs2 + r * 33 + kq * 4;
            d[0] = make_float2(v.x, v.x);
            d[1] = make_float2(v.y, v.y);
            d[2] = make_float2(v.z, v.z);
            d[3] = make_float2(v.w, v.w);
        }
        __syncthreads();

        const float2* xb = Xs2 + (ty * 4) * 33;
        #pragma unroll 8
        for (int k = 0; k < BK; k++) {
            ull x0 = *(const ull*)(xb + k);
            ull x1 = *(const ull*)(xb + 33 + k);
            ull x2 = *(const ull*)(xb + 66 + k);
            ull x3 = *(const ull*)(xb + 99 + k);
            const ull* wp = (const ull*)(Ws + k * 64 + tx * 8);
            ulonglong2 wa = *(const ulonglong2*)wp;
            ulonglong2 wb = *(const ulonglong2*)(wp + 2);
            ffma2(acc[0][0], x0, wa.x); ffma2(acc[0][1], x0, wa.y);
            ffma2(acc[0][2], x0, wb.x); ffma2(acc[0][3], x0, wb.y);
            ffma2(acc[1][0], x1, wa.x); ffma2(acc[1][1], x1, wa.y);
            ffma2(acc[1][2], x1, wb.x); ffma2(acc[1][3], x1, wb.y);
            ffma2(acc[2][0], x2, wa.x); ffma2(acc[2][1], x2, wa.y);
            ffma2(acc[2][2], x2, wb.x); ffma2(acc[2][3], x2, wb.y);
            ffma2(acc[3][0], x3, wa.x); ffma2(acc[3][1], x3, wa.y);
            ffma2(acc[3][2], x3, wb.x); ffma2(acc[3][3], x3, wb.y);
        }
        __syncthreads();
    }

    #pragma unroll
    for (int i = 0; i < 4; i++) {
        int row = row0 + ty * 4 + i;
        if (row < N_NODES) {
            float2 p0 = u2f2(acc[i][0]), p1 = u2f2(acc[i][1]);
            float2 p2 = u2f2(acc[i][2]), p3 = u2f2(acc[i][3]);
            float4* o = (float4*)(g_h1 + (size_t)row * HID + tx * 8);
            o[0] = make_float4(p0.x, p0.y, p1.x, p1.y);
            o[1] = make_float4(p2.x, p2.y, p3.x, p3.y);
        }
    }
}

// GEMM2: g_h2[N,40] = g_a1[N,64] @ W2[64,40], f32x2 path, 1 row/thread
__global__ __launch_bounds__(128) void k_gemm2(const float* __restrict__ W2) {
    __shared__ __align__(16) float Ws[HID * DOUT];  // 10 KB
    __shared__ float Xs[128 * 65];                  // 33.3 KB
    int tid = threadIdx.x;
    int row0 = blockIdx.x * 128;

    #pragma unroll
    for (int i = tid; i < HID * DOUT / 4; i += 128)
        ((float4*)Ws)[i] = ((const float4*)W2)[i];
    for (int i = tid; i < 128 * 16; i += 128) {
        int r = i >> 4, kv = i & 15;
        int row = row0 + r;
        float4 v = make_float4(0.f, 0.f, 0.f, 0.f);
        if (row < N_NODES)
            v = *(const float4*)(g_a1 + (size_t)row * HID + kv * 4);
        float* p = Xs + r * 65 + kv * 4;
        p[0] = v.x; p[1] = v.y; p[2] = v.z; p[3] = v.w;
    }
    __syncthreads();

    ull acc[20];
    #pragma unroll
    for (int j = 0; j < 20; j++) acc[j] = 0ull;
    const float* xr = Xs + tid * 65;
    #pragma unroll 4
    for (int k = 0; k < HID; k++) {
        ull xp = fpack(xr[k]);
        const ulonglong2* wr = (const ulonglong2*)(Ws + k * DOUT);
        #pragma unroll
        for (int j = 0; j < 10; j++) {
            ulonglong2 w = wr[j];
            ffma2(acc[2 * j], xp, w.x);
            ffma2(acc[2 * j + 1], xp, w.y);
        }
    }
    int row = row0 + tid;
    if (row < N_NODES) {
        float4* o = (float4*)(g_h2 + (size_t)row * DOUT);
        #pragma unroll
        for (int j = 0; j < 10; j++) {
            float2 a = u2f2(acc[2 * j]), b = u2f2(acc[2 * j + 1]);
            o[j] = make_float4(a.x, a.y, b.x, b.y);
        }
    }
}

// ---------------------------------------------------------------
__global__ __launch_bounds__(256) void k_agg1(const float* __restrict__ b1) {
    int v = (blockIdx.x * blockDim.x + threadIdx.x) >> 5;
    int lane = threadIdx.x & 31;
    if (v >= N_NODES) return;
    float dv = g_dinv[v];
    float2 acc = ((const float2*)(g_h1 + (size_t)v * HID))[lane];
    float sw = dv * dv;
    acc.x *= sw; acc.y *= sw;
    int start = g_rowptr[v], end = g_rowptr[v + 1];
    for (int base = start; base < end; base += 32) {
        int e = base + lane;
        int s = 0; float w = 0.f;
        if (e < end) { s = g_col[e]; w = g_dinv[s] * dv; }
        int cnt = min(32, end - base);
        #pragma unroll 4
        for (int j = 0; j < cnt; j++) {
            int   ss = __shfl_sync(0xffffffffu, s, j);
            float ww = __shfl_sync(0xffffffffu, w, j);
            float2 hh = ((const float2*)(g_h1 + (size_t)ss * HID))[lane];
            acc.x = fmaf(ww, hh.x, acc.x);
            acc.y = fmaf(ww, hh.y, acc.y);
        }
    }
    float2 bb = ((const float2*)b1)[lane];
    acc.x = fmaxf(acc.x + bb.x, 0.f);
    acc.y = fmaxf(acc.y + bb.y, 0.f);
    ((float2*)(g_a1 + (size_t)v * HID))[lane] = acc;
}

__global__ __launch_bounds__(256) void k_agg2(const float* __restrict__ b2,
                                              float* __restrict__ out) {
    int v = (blockIdx.x * blockDim.x + threadIdx.x) >> 5;
    int lane = threadIdx.x & 31;
    if (v >= N_NODES) return;
    float dv = g_dinv[v];
    bool p2 = lane < (DOUT - 32);
    const float* hv = g_h2 + (size_t)v * DOUT;
    float sw = dv * dv;
    float a0 = hv[lane] * sw;
    float a1 = p2 ? hv[32 + lane] * sw : 0.f;
    int start = g_rowptr[v], end = g_rowptr[v + 1];
    for (int base = start; base < end; base += 32) {
        int e = base + lane;
        int s = 0; float w = 0.f;
        if (e < end) { s = g_col[e]; w = g_dinv[s] * dv; }
        int cnt = min(32, end - base);
        #pragma unroll 4
        for (int j = 0; j < cnt; j++) {
            int   ss = __shfl_sync(0xffffffffu, s, j);
            float ww = __shfl_sync(0xffffffffu, w, j);
            const float* hs = g_h2 + (size_t)ss * DOUT;
            a0 = fmaf(ww, hs[lane], a0);
            if (p2) a1 = fmaf(ww, hs[32 + lane], a1);
        }
    }
    float* ov = out + (size_t)v * DOUT;
    ov[lane] = a0 + b2[lane];
    if (p2) ov[32 + lane] = a1 + b2[32 + lane];
}

// ---------------------------------------------------------------
extern "C" void kernel_launch(void* const* d_in, const int* in_sizes, int n_in,
                              void* d_out, int out_size) {
    const float* x  = (const float*)d_in[0];
    const float* W1 = (const float*)d_in[1];
    const float* b1 = (const float*)d_in[2];
    const float* W2 = (const float*)d_in[3];
    const float* b2 = (const float*)d_in[4];
    const int*   ei = (const int*)d_in[5];
    float* out = (float*)d_out;

    k_zero_cnt<<<(N_NODES + 255) / 256, 256>>>();
    k_count<<<(N_EDGES + 255) / 256, 256>>>(ei);
    k_scanA<<<SCAN_BLOCKS, 1024>>>();
    k_scanB<<<1, 32>>>();
    k_scanC<<<(N_NODES + 255) / 256, 256>>>();
    k_fill_gemm1<<<GEMM1_BLOCKS + FILL_BLOCKS, 256>>>(ei, x, W1);
    k_agg1<<<(N_NODES * 32 + 255) / 256, 256>>>(b1);
    k_gemm2<<<(N_NODES + 127) / 128, 128>>>(W2);
    k_agg2<<<(N_NODES * 32 + 255) / 256, 256>>>(b2, out);
}